// round 4
// baseline (speedup 1.0000x reference)
#include <cuda_runtime.h>
#include <math.h>

#define NN   20000
#define DD   128
#define EE   60000
#define PERL 4000
#define NB   20   // (level-1)*5 + t, level 1..4, t 0..4

// ---------------- device scratch (no allocation allowed) ----------------
__device__ float g_aggs[NN * DD];
__device__ float g_aggf[NN * DD];
__device__ float g_Ws1t[5 * DD * DD];
__device__ float g_Ws2t[5 * DD * DD];
__device__ float g_Wf1t[4 * 2 * DD * DD];
__device__ float g_Wf2t[4 * DD * DD];
__device__ float g_Wnf1t[DD * DD];
__device__ float g_Wnf2t[DD * DD];
__device__ float g_Gswih_t[5 * 3 * DD * DD];
__device__ float g_Gfwih_t[5 * 3 * DD * DD];
__device__ int g_esrc[EE];
__device__ int g_edst[EE];
__device__ int g_ecnt[NB];   // statically zero; re-zeroed by k_scan after read
__device__ int g_eoff[NB + 1];
__device__ int g_ecur[NB];
__device__ int g_nodes[NN];
__device__ int g_ncnt[NB];
__device__ int g_noff[NB + 1];
__device__ int g_ncur[NB];

// CODES = [3,2,5,1,4] -> t index; code c in 1..5
__device__ __forceinline__ int code2t(int c) {
    switch (c) {
        case 1: return 3;
        case 2: return 1;
        case 3: return 0;
        case 4: return 4;
        default: return 2; // 5
    }
}
__device__ __forceinline__ float sigmoidf_(float x) { return 1.f / (1.f + expf(-x)); }

// packed f32x2 FMA (sm_100+): d = a*b + d on both lanes
__device__ __forceinline__ void fma2(unsigned long long& d, unsigned long long a,
                                     unsigned long long b) {
    asm("fma.rn.f32x2 %0, %1, %2, %0;" : "+l"(d) : "l"(a), "l"(b));
}
__device__ __forceinline__ float unpack_sum(unsigned long long a) {
    float lo, hi;
    asm("mov.b64 {%0, %1}, %2;" : "=f"(lo), "=f"(hi) : "l"(a));
    return lo + hi;
}

// ---------------- prep: init + count + weight transposes (fused) ----------
__device__ __forceinline__ void tr1(const float* __restrict__ src, float* __restrict__ dst,
                                    int idx, int K, int J) {
    int m = idx / (K * J);
    int r = idx - m * (K * J);
    int k = r / J;
    int j = r - k * J;
    dst[m * K * J + j * K + k] = src[idx];
}

#define INIT_TOTAL (NN * DD)
#define PREP_TOTAL 884736
__global__ void k_init(const float* __restrict__ hs_init, const int* __restrict__ gate,
                       float* __restrict__ hs, float* __restrict__ hf,
                       const float* __restrict__ Ws1, const float* __restrict__ Ws2,
                       const float* __restrict__ Wf1, const float* __restrict__ Wf2,
                       const float* __restrict__ Wnf1, const float* __restrict__ Wnf2,
                       const float* __restrict__ Gs, const float* __restrict__ Gf,
                       const int* __restrict__ ei, const int* __restrict__ flev) {
    int stride = gridDim.x * blockDim.x;
    int tid0 = blockIdx.x * blockDim.x + threadIdx.x;
    // counting pass (g_ecnt/g_ncnt are zero: static init on call 0, k_scan re-zeroes after)
    {
        int i = tid0;
        if (i < EE) {
            int dst = ei[EE + i];
            int b = (flev[dst] - 1) * 5 + code2t(gate[dst]);
            atomicAdd(&g_ecnt[b], 1);
        }
        int v = i + PERL;
        if (i < NN - PERL) {
            int b = (flev[v] - 1) * 5 + code2t(gate[v]);
            atomicAdd(&g_ncnt[b], 1);
        }
    }
    for (int i = tid0; i < INIT_TOTAL; i += stride) {
        int v = i >> 7;
        hs[i] = (gate[v] == 0) ? hs_init[i] : 0.f;
        hf[i] = 0.f;
        g_aggs[i] = 0.f;
        g_aggf[i] = 0.f;
    }
    for (int i = tid0; i < PREP_TOTAL; i += stride) {
        int idx = i;
        if (idx < 81920) { tr1(Ws1, g_Ws1t, idx, 128, 128); continue; }
        idx -= 81920;
        if (idx < 81920) { tr1(Ws2, g_Ws2t, idx, 128, 128); continue; }
        idx -= 81920;
        if (idx < 131072) { tr1(Wf1, g_Wf1t, idx, 256, 128); continue; }
        idx -= 131072;
        if (idx < 65536) { tr1(Wf2, g_Wf2t, idx, 128, 128); continue; }
        idx -= 65536;
        if (idx < 16384) { tr1(Wnf1, g_Wnf1t, idx, 128, 128); continue; }
        idx -= 16384;
        if (idx < 16384) { tr1(Wnf2, g_Wnf2t, idx, 128, 128); continue; }
        idx -= 16384;
        if (idx < 245760) { tr1(Gs, g_Gswih_t, idx, 128, 384); continue; }
        idx -= 245760;
        tr1(Gf, g_Gfwih_t, idx, 128, 384);
    }
}

__global__ void k_scan() {
    if (threadIdx.x == 0 && blockIdx.x == 0) {
        int s = 0, t = 0;
        for (int b = 0; b < NB; b++) {
            g_eoff[b] = s; g_ecur[b] = s; s += g_ecnt[b];
            g_noff[b] = t; g_ncur[b] = t; t += g_ncnt[b];
            g_ecnt[b] = 0;  // re-zero for next graph replay (deterministic)
            g_ncnt[b] = 0;
        }
        g_eoff[NB] = s;
        g_noff[NB] = t;
    }
}

__global__ void k_scatter(const int* __restrict__ ei, const int* __restrict__ gate,
                          const int* __restrict__ flev) {
    int i = blockIdx.x * blockDim.x + threadIdx.x;
    if (i < EE) {
        int src = ei[i], dst = ei[EE + i];
        int b = (flev[dst] - 1) * 5 + code2t(gate[dst]);
        int p = atomicAdd(&g_ecur[b], 1);
        g_esrc[p] = src;
        g_edst[p] = dst;
    }
    int v = i + PERL;
    if (i < NN - PERL) {
        int b = (flev[v] - 1) * 5 + code2t(gate[v]);
        int p = atomicAdd(&g_ncur[b], 1);
        g_nodes[p] = v;
    }
}

// stage transposed weights into smem; f4 slot c in row goes to c ^ (row & 7).
__device__ __forceinline__ void stage_w(float* __restrict__ dst, const float* __restrict__ src,
                                        int rows, int k4n, int tid, int nthr) {
    float4* d = (float4*)dst;
    const float4* sp = (const float4*)src;
    int tot = rows * k4n;
    for (int i = tid; i < tot; i += nthr) {
        int row = i / k4n;
        int c = i - row * k4n;
        d[row * k4n + (c ^ (row & 7))] = sp[i];
    }
}

// ---------------- packed-FMA warp GEMM (compile-time K) ----------------
// sW swizzled [NOUT*32 rows][K4N 16B-chunks]; lane owns output rows oi*32+lane.
// sX unswizzled, G rows of XS4 chunks; broadcast reads.
template <int G, int NOUT, int K4N, int XS4>
__device__ __forceinline__ void gemm_p(const float* __restrict__ sW,
                                       const float* __restrict__ sX, int lane,
                                       unsigned long long (&acc)[G][NOUT]) {
    const ulonglong2* wU = (const ulonglong2*)sW;
    const ulonglong2* xU = (const ulonglong2*)sX;
    int s = lane & 7;
#pragma unroll
    for (int g = 0; g < G; g++)
#pragma unroll
        for (int oi = 0; oi < NOUT; oi++) acc[g][oi] = 0ull;
#pragma unroll 8
    for (int k4 = 0; k4 < K4N; k4++) {
        int kk = k4 ^ s;
        ulonglong2 xv[G];
#pragma unroll
        for (int g = 0; g < G; g++) xv[g] = xU[g * XS4 + k4];
#pragma unroll
        for (int oi = 0; oi < NOUT; oi++) {
            ulonglong2 wv = wU[(oi * 32 + lane) * K4N + kk];
#pragma unroll
            for (int g = 0; g < G; g++) {
                fma2(acc[g][oi], xv[g].x, wv.x);
                fma2(acc[g][oi], xv[g].y, wv.y);
            }
        }
    }
}

// ---------------- edge structural MLP (16 warps for latency hiding) -------
#define ES_NW 16
#define ES_G 8
// smem floats: 16384 + 16384 + 16*8*128 = 49152 -> 196608 B
__global__ void __launch_bounds__(512, 1)
k_edge_struct(const float* __restrict__ hs, const float* __restrict__ bs1,
              const float* __restrict__ bs2, int level) {
    extern __shared__ float sm[];
    float* sW1 = sm;
    float* sW2 = sm + 16384;
    float* sX = sm + 32768;

    int t = blockIdx.y;
    int b = (level - 1) * 5 + t;
    int eS = g_eoff[b], cnt = g_eoff[b + 1] - eS;

    stage_w(sW1, g_Ws1t + t * 16384, 128, 32, threadIdx.x, 512);
    stage_w(sW2, g_Ws2t + t * 16384, 128, 32, threadIdx.x, 512);
    __syncthreads();

    int w = threadIdx.x >> 5, lane = threadIdx.x & 31;
    float b1v[4], b2v[4];
#pragma unroll
    for (int oi = 0; oi < 4; oi++) {
        b1v[oi] = bs1[t * 128 + oi * 32 + lane];
        b2v[oi] = bs2[t * 128 + oi * 32 + lane];
    }
    // even per-warp partition of this bucket
    int nw = gridDim.x * ES_NW;
    int wg = blockIdx.x * ES_NW + w;
    int ws = eS + (int)(((long long)cnt * wg) / nw);
    int we = eS + (int)(((long long)cnt * (wg + 1)) / nw);
    float* myX = sX + w * ES_G * 128;

    for (int base = ws; base < we; base += ES_G) {
        int ne = min(ES_G, we - base);
#pragma unroll
        for (int g = 0; g < ES_G; g++) {
            float4 xv = make_float4(0.f, 0.f, 0.f, 0.f);
            if (g < ne) {
                int sn = g_esrc[base + g];
                xv = ((const float4*)(hs + sn * 128))[lane];
            }
            ((float4*)(myX + g * 128))[lane] = xv;
        }
        __syncwarp();
        unsigned long long a1[ES_G][4];
        gemm_p<ES_G, 4, 32, 32>(sW1, myX, lane, a1);
        __syncwarp();
#pragma unroll
        for (int g = 0; g < ES_G; g++)
#pragma unroll
            for (int oi = 0; oi < 4; oi++)
                myX[g * 128 + oi * 32 + lane] = fmaxf(unpack_sum(a1[g][oi]) + b1v[oi], 0.f);
        __syncwarp();
        unsigned long long a2[ES_G][4];
        gemm_p<ES_G, 4, 32, 32>(sW2, myX, lane, a2);
#pragma unroll
        for (int g = 0; g < ES_G; g++) {
            if (g < ne) {
                int dv = g_edst[base + g];
#pragma unroll
                for (int oi = 0; oi < 4; oi++)
                    atomicAdd(&g_aggs[dv * 128 + oi * 32 + lane],
                              unpack_sum(a2[g][oi]) + b2v[oi]);
            }
        }
        __syncwarp();
    }
}

// ---------------- edge functional MLP (8 warps, G=4) ----------------
#define EF_NW 8
#define EF_G 4
// smem floats: 32768 + 16384 + 8*4*256 = 57344 -> 229376 B
__global__ void __launch_bounds__(256, 1)
k_edge_func(const float* __restrict__ hs, const float* __restrict__ hf,
            const float* __restrict__ bf1, const float* __restrict__ bf2,
            const float* __restrict__ bnf1, const float* __restrict__ bnf2, int level) {
    extern __shared__ float sm[];
    float* sW1 = sm;          // up to 32768 floats (swizzled)
    float* sW2 = sm + 32768;  // 16384 floats
    float* sX = sm + 49152;   // 8*4*256 floats

    int t = blockIdx.y;
    int b = (level - 1) * 5 + t;
    int eS = g_eoff[b], cnt = g_eoff[b + 1] - eS;
    bool isnot = (t == 1);

    const float *W1g, *W2g, *b1g, *b2g;
    if (isnot) {
        W1g = g_Wnf1t; W2g = g_Wnf2t; b1g = bnf1; b2g = bnf2;
    } else {
        int fi = (t == 0) ? 0 : (t == 2) ? 1 : (t == 3) ? 2 : 3;
        W1g = g_Wf1t + fi * 32768;
        W2g = g_Wf2t + fi * 16384;
        b1g = bf1 + fi * 128;
        b2g = bf2 + fi * 128;
    }
    stage_w(sW1, W1g, 128, isnot ? 32 : 64, threadIdx.x, 256);
    stage_w(sW2, W2g, 128, 32, threadIdx.x, 256);
    __syncthreads();

    int w = threadIdx.x >> 5, lane = threadIdx.x & 31;
    float b1v[4], b2v[4];
#pragma unroll
    for (int oi = 0; oi < 4; oi++) {
        b1v[oi] = b1g[oi * 32 + lane];
        b2v[oi] = b2g[oi * 32 + lane];
    }
    int nw = gridDim.x * EF_NW;
    int wg = blockIdx.x * EF_NW + w;
    int ws = eS + (int)(((long long)cnt * wg) / nw);
    int we = eS + (int)(((long long)cnt * (wg + 1)) / nw);
    float* myX = sX + w * EF_G * 256;

    for (int base = ws; base < we; base += EF_G) {
        int ne = min(EF_G, we - base);
#pragma unroll
        for (int g = 0; g < EF_G; g++) {
            float4 xa = make_float4(0.f, 0.f, 0.f, 0.f);
            float4 xb = xa;
            if (g < ne) {
                int sn = g_esrc[base + g];
                if (isnot) {
                    xa = ((const float4*)(hf + sn * 128))[lane];
                } else {
                    xa = ((const float4*)(hs + sn * 128))[lane];
                    xb = ((const float4*)(hf + sn * 128))[lane];
                }
            }
            ((float4*)(myX + g * 256))[lane] = xa;
            if (!isnot) ((float4*)(myX + g * 256))[32 + lane] = xb;
        }
        __syncwarp();
        unsigned long long a1[EF_G][4];
        if (isnot)
            gemm_p<EF_G, 4, 32, 64>(sW1, myX, lane, a1);
        else
            gemm_p<EF_G, 4, 64, 64>(sW1, myX, lane, a1);
        __syncwarp();
#pragma unroll
        for (int g = 0; g < EF_G; g++)
#pragma unroll
            for (int oi = 0; oi < 4; oi++)
                myX[g * 256 + oi * 32 + lane] = fmaxf(unpack_sum(a1[g][oi]) + b1v[oi], 0.f);
        __syncwarp();
        unsigned long long a2[EF_G][4];
        gemm_p<EF_G, 4, 32, 64>(sW2, myX, lane, a2);
#pragma unroll
        for (int g = 0; g < EF_G; g++) {
            if (g < ne) {
                int dv = g_edst[base + g];
#pragma unroll
                for (int oi = 0; oi < 4; oi++)
                    atomicAdd(&g_aggf[dv * 128 + oi * 32 + lane],
                              unpack_sum(a2[g][oi]) + b2v[oi]);
            }
        }
        __syncwarp();
    }
}

// ---------------- GRU (h == 0), fused s/f via blockIdx.y ----------------
#define GR_NW 8
#define GR_G 4
// smem floats: 49152 + 8*4*128 = 53248 -> 212992 B
__global__ void __launch_bounds__(256, 1)
k_gru(const float* __restrict__ Gs_bih, const float* __restrict__ Gs_bhh,
      const float* __restrict__ Gf_bih, const float* __restrict__ Gf_bhh,
      float* __restrict__ hs, float* __restrict__ hf, int level) {
    extern __shared__ float sm[];
    float* sW = sm;           // [384][128] swizzled wih
    float* sX = sm + 49152;

    int t = blockIdx.y % 5;
    int isF = blockIdx.y / 5;
    int b = (level - 1) * 5 + t;
    int nS = g_noff[b], cnt = g_noff[b + 1] - nS;

    const float* agg = isF ? g_aggf : g_aggs;
    float* hout = isF ? hf : hs;
    const float* wgp = (isF ? g_Gfwih_t : g_Gswih_t) + t * 49152;
    const float* bih = (isF ? Gf_bih : Gs_bih) + t * 384;
    const float* bhh = (isF ? Gf_bhh : Gs_bhh) + t * 384;

    stage_w(sW, wgp, 384, 32, threadIdx.x, 256);
    __syncthreads();

    int w = threadIdx.x >> 5, lane = threadIdx.x & 31;
    float bR[4], bZ[4], bNi[4], bNh[4];
#pragma unroll
    for (int oi = 0; oi < 4; oi++) {
        int j = oi * 32 + lane;
        bR[oi] = bih[j] + bhh[j];
        bZ[oi] = bih[128 + j] + bhh[128 + j];
        bNi[oi] = bih[256 + j];
        bNh[oi] = bhh[256 + j];
    }
    int nw = gridDim.x * GR_NW;
    int wg = blockIdx.x * GR_NW + w;
    int ws = nS + (int)(((long long)cnt * wg) / nw);
    int we = nS + (int)(((long long)cnt * (wg + 1)) / nw);
    float* myX = sX + w * GR_G * 128;

    for (int base = ws; base < we; base += GR_G) {
        int nn = min(GR_G, we - base);
        int nodes[GR_G];
#pragma unroll
        for (int g = 0; g < GR_G; g++) {
            float4 xv = make_float4(0.f, 0.f, 0.f, 0.f);
            nodes[g] = 0;
            if (g < nn) {
                nodes[g] = g_nodes[base + g];
                xv = ((const float4*)(agg + nodes[g] * 128))[lane];
            }
            ((float4*)(myX + g * 128))[lane] = xv;
        }
        __syncwarp();

        unsigned long long acc[GR_G][12];
        gemm_p<GR_G, 12, 32, 32>(sW, myX, lane, acc);

#pragma unroll
        for (int g = 0; g < GR_G; g++) {
            if (g < nn) {
#pragma unroll
                for (int oi = 0; oi < 4; oi++) {
                    float r = sigmoidf_(unpack_sum(acc[g][oi]) + bR[oi]);
                    float z = sigmoidf_(unpack_sum(acc[g][oi + 4]) + bZ[oi]);
                    float n = tanhf(unpack_sum(acc[g][oi + 8]) + bNi[oi] + r * bNh[oi]);
                    hout[nodes[g] * 128 + oi * 32 + lane] = (1.f - z) * n;
                }
            }
        }
        __syncwarp();
    }
}

// ---------------- host launch ----------------
extern "C" void kernel_launch(void* const* d_in, const int* in_sizes, int n_in,
                              void* d_out, int out_size) {
    const float* hs_init = (const float*)d_in[0];
    const float* Ws1 = (const float*)d_in[1];
    const float* bs1 = (const float*)d_in[2];
    const float* Ws2 = (const float*)d_in[3];
    const float* bs2 = (const float*)d_in[4];
    const float* Wf1 = (const float*)d_in[5];
    const float* bf1 = (const float*)d_in[6];
    const float* Wf2 = (const float*)d_in[7];
    const float* bf2 = (const float*)d_in[8];
    const float* Wnf1 = (const float*)d_in[9];
    const float* bnf1 = (const float*)d_in[10];
    const float* Wnf2 = (const float*)d_in[11];
    const float* bnf2 = (const float*)d_in[12];
    const float* Gs_wih = (const float*)d_in[13];
    // d_in[14] = Gs_whh (unused: h == 0)
    const float* Gs_bih = (const float*)d_in[15];
    const float* Gs_bhh = (const float*)d_in[16];
    const float* Gf_wih = (const float*)d_in[17];
    // d_in[18] = Gf_whh (unused)
    const float* Gf_bih = (const float*)d_in[19];
    const float* Gf_bhh = (const float*)d_in[20];
    const int* edge_index = (const int*)d_in[21];
    const int* gate = (const int*)d_in[22];
    const int* flev = (const int*)d_in[23];

    float* hs = (float*)d_out;
    float* hf = hs + NN * DD;

    cudaFuncSetAttribute(k_edge_struct, cudaFuncAttributeMaxDynamicSharedMemorySize, 196608);
    cudaFuncSetAttribute(k_edge_func, cudaFuncAttributeMaxDynamicSharedMemorySize, 229376);
    cudaFuncSetAttribute(k_gru, cudaFuncAttributeMaxDynamicSharedMemorySize, 212992);

    k_init<<<1024, 256>>>(hs_init, gate, hs, hf, Ws1, Ws2, Wf1, Wf2, Wnf1, Wnf2,
                          Gs_wih, Gf_wih, edge_index, flev);
    k_scan<<<1, 1>>>();
    k_scatter<<<(EE + 255) / 256, 256>>>(edge_index, gate, flev);

    for (int level = 1; level < 5; level++) {
        k_edge_struct<<<dim3(29, 5), 512, 196608>>>(hs, bs1, bs2, level);
        k_edge_func<<<dim3(29, 5), 256, 229376>>>(hs, hf, bf1, bf2, bnf1, bnf2, level);
        k_gru<<<dim3(14, 10), 256, 212992>>>(Gs_bih, Gs_bhh, Gf_bih, Gf_bhh, hs, hf, level);
    }
}

// round 5
// speedup vs baseline: 1.0419x; 1.0419x over previous
#include <cuda_runtime.h>
#include <math.h>

#define NN   20000
#define DD   128
#define EE   60000
#define PERL 4000
#define NB   20   // (level-1)*5 + t, level 1..4, t 0..4

// ---------------- device scratch (no allocation allowed) ----------------
__device__ float g_aggs[NN * DD];
__device__ float g_aggf[NN * DD];
__device__ float g_Ws1t[5 * DD * DD];
__device__ float g_Ws2t[5 * DD * DD];
__device__ float g_Wf1t[4 * 2 * DD * DD];
__device__ float g_Wf2t[4 * DD * DD];
__device__ float g_Wnf1t[DD * DD];
__device__ float g_Wnf2t[DD * DD];
__device__ float g_Gswih_t[5 * 3 * DD * DD];
__device__ float g_Gfwih_t[5 * 3 * DD * DD];
__device__ int g_esrc[EE];
__device__ int g_edst[EE];
__device__ int g_ecnt[NB];   // statically zero; re-zeroed by k_scan after read
__device__ int g_eoff[NB + 1];
__device__ int g_ecur[NB];
__device__ int g_nodes[NN];
__device__ int g_ncnt[NB];
__device__ int g_noff[NB + 1];
__device__ int g_ncur[NB];

// CODES = [3,2,5,1,4] -> t index; code c in 1..5
__device__ __forceinline__ int code2t(int c) {
    switch (c) {
        case 1: return 3;
        case 2: return 1;
        case 3: return 0;
        case 4: return 4;
        default: return 2; // 5
    }
}
__device__ __forceinline__ float sigmoidf_(float x) { return 1.f / (1.f + expf(-x)); }

// packed f32x2 FMA (sm_100+): d = a*b + d on both lanes
__device__ __forceinline__ void fma2(unsigned long long& d, unsigned long long a,
                                     unsigned long long b) {
    asm("fma.rn.f32x2 %0, %1, %2, %0;" : "+l"(d) : "l"(a), "l"(b));
}
__device__ __forceinline__ float unpack_sum(unsigned long long a) {
    float lo, hi;
    asm("mov.b64 {%0, %1}, %2;" : "=f"(lo), "=f"(hi) : "l"(a));
    return lo + hi;
}

// ---------------- prep: init + count + weight transposes (fused) ----------
__device__ __forceinline__ void tr1(const float* __restrict__ src, float* __restrict__ dst,
                                    int idx, int K, int J) {
    int m = idx / (K * J);
    int r = idx - m * (K * J);
    int k = r / J;
    int j = r - k * J;
    dst[m * K * J + j * K + k] = src[idx];
}

#define INIT_TOTAL (NN * DD)
#define PREP_TOTAL 884736
__global__ void k_init(const float* __restrict__ hs_init, const int* __restrict__ gate,
                       float* __restrict__ hs, float* __restrict__ hf,
                       const float* __restrict__ Ws1, const float* __restrict__ Ws2,
                       const float* __restrict__ Wf1, const float* __restrict__ Wf2,
                       const float* __restrict__ Wnf1, const float* __restrict__ Wnf2,
                       const float* __restrict__ Gs, const float* __restrict__ Gf,
                       const int* __restrict__ ei, const int* __restrict__ flev) {
    int stride = gridDim.x * blockDim.x;
    int tid0 = blockIdx.x * blockDim.x + threadIdx.x;
    // counting pass (g_ecnt/g_ncnt are zero: static init on call 0, k_scan re-zeroes after)
    {
        int i = tid0;
        if (i < EE) {
            int dst = ei[EE + i];
            int b = (flev[dst] - 1) * 5 + code2t(gate[dst]);
            atomicAdd(&g_ecnt[b], 1);
        }
        int v = i + PERL;
        if (i < NN - PERL) {
            int b = (flev[v] - 1) * 5 + code2t(gate[v]);
            atomicAdd(&g_ncnt[b], 1);
        }
    }
    for (int i = tid0; i < INIT_TOTAL; i += stride) {
        int v = i >> 7;
        hs[i] = (gate[v] == 0) ? hs_init[i] : 0.f;
        hf[i] = 0.f;
        g_aggs[i] = 0.f;
        g_aggf[i] = 0.f;
    }
    for (int i = tid0; i < PREP_TOTAL; i += stride) {
        int idx = i;
        if (idx < 81920) { tr1(Ws1, g_Ws1t, idx, 128, 128); continue; }
        idx -= 81920;
        if (idx < 81920) { tr1(Ws2, g_Ws2t, idx, 128, 128); continue; }
        idx -= 81920;
        if (idx < 131072) { tr1(Wf1, g_Wf1t, idx, 256, 128); continue; }
        idx -= 131072;
        if (idx < 65536) { tr1(Wf2, g_Wf2t, idx, 128, 128); continue; }
        idx -= 65536;
        if (idx < 16384) { tr1(Wnf1, g_Wnf1t, idx, 128, 128); continue; }
        idx -= 16384;
        if (idx < 16384) { tr1(Wnf2, g_Wnf2t, idx, 128, 128); continue; }
        idx -= 16384;
        if (idx < 245760) { tr1(Gs, g_Gswih_t, idx, 128, 384); continue; }
        idx -= 245760;
        tr1(Gf, g_Gfwih_t, idx, 128, 384);
    }
}

__global__ void k_scan() {
    if (threadIdx.x == 0 && blockIdx.x == 0) {
        int s = 0, t = 0;
        for (int b = 0; b < NB; b++) {
            g_eoff[b] = s; g_ecur[b] = s; s += g_ecnt[b];
            g_noff[b] = t; g_ncur[b] = t; t += g_ncnt[b];
            g_ecnt[b] = 0;  // re-zero for next graph replay (deterministic)
            g_ncnt[b] = 0;
        }
        g_eoff[NB] = s;
        g_noff[NB] = t;
    }
}

__global__ void k_scatter(const int* __restrict__ ei, const int* __restrict__ gate,
                          const int* __restrict__ flev) {
    int i = blockIdx.x * blockDim.x + threadIdx.x;
    if (i < EE) {
        int src = ei[i], dst = ei[EE + i];
        int b = (flev[dst] - 1) * 5 + code2t(gate[dst]);
        int p = atomicAdd(&g_ecur[b], 1);
        g_esrc[p] = src;
        g_edst[p] = dst;
    }
    int v = i + PERL;
    if (i < NN - PERL) {
        int b = (flev[v] - 1) * 5 + code2t(gate[v]);
        int p = atomicAdd(&g_ncur[b], 1);
        g_nodes[p] = v;
    }
}

// stage transposed weights into smem; f4 slot c in row goes to c ^ (row & 7).
__device__ __forceinline__ void stage_w(float* __restrict__ dst, const float* __restrict__ src,
                                        int rows, int k4n, int tid, int nthr) {
    float4* d = (float4*)dst;
    const float4* sp = (const float4*)src;
    int tot = rows * k4n;
    for (int i = tid; i < tot; i += nthr) {
        int row = i / k4n;
        int c = i - row * k4n;
        d[row * k4n + (c ^ (row & 7))] = sp[i];
    }
}

// ---------------- packed-FMA warp GEMM (compile-time K) ----------------
// sW swizzled [NOUT*32 rows][K4N 16B-chunks]; lane owns output rows oi*32+lane.
// sX unswizzled, G rows of XS4 chunks; broadcast reads.
template <int G, int NOUT, int K4N, int XS4>
__device__ __forceinline__ void gemm_p(const float* __restrict__ sW,
                                       const float* __restrict__ sX, int lane,
                                       unsigned long long (&acc)[G][NOUT]) {
    const ulonglong2* wU = (const ulonglong2*)sW;
    const ulonglong2* xU = (const ulonglong2*)sX;
    int s = lane & 7;
#pragma unroll
    for (int g = 0; g < G; g++)
#pragma unroll
        for (int oi = 0; oi < NOUT; oi++) acc[g][oi] = 0ull;
#pragma unroll 8
    for (int k4 = 0; k4 < K4N; k4++) {
        int kk = k4 ^ s;
        ulonglong2 xv[G];
#pragma unroll
        for (int g = 0; g < G; g++) xv[g] = xU[g * XS4 + k4];
#pragma unroll
        for (int oi = 0; oi < NOUT; oi++) {
            ulonglong2 wv = wU[(oi * 32 + lane) * K4N + kk];
#pragma unroll
            for (int g = 0; g < G; g++) {
                fma2(acc[g][oi], xv[g].x, wv.x);
                fma2(acc[g][oi], xv[g].y, wv.y);
            }
        }
    }
}

// ---------------- fused edge kernel: y<5 struct, y>=5 func --------------
#define E_NW 8
// smem floats: 32768(sW1) + 16384(sW2) + 8*1024(sX) = 57344 -> 229376 B
__global__ void __launch_bounds__(256, 1)
k_edges(const float* __restrict__ hs, const float* __restrict__ hf,
        const float* __restrict__ bs1, const float* __restrict__ bs2,
        const float* __restrict__ bf1, const float* __restrict__ bf2,
        const float* __restrict__ bnf1, const float* __restrict__ bnf2, int level) {
    extern __shared__ float sm[];
    float* sW1 = sm;
    float* sW2 = sm + 32768;
    float* sX = sm + 49152;

    int y = blockIdx.y;
    bool isStruct = (y < 5);
    int t = isStruct ? y : y - 5;
    int b = (level - 1) * 5 + t;
    int eS = g_eoff[b], cnt = g_eoff[b + 1] - eS;

    int w = threadIdx.x >> 5, lane = threadIdx.x & 31;
    int nw = gridDim.x * E_NW;
    int wgi = blockIdx.x * E_NW + w;
    int ws = eS + (int)(((long long)cnt * wgi) / nw);
    int we = eS + (int)(((long long)cnt * (wgi + 1)) / nw);
    float* myX = sX + w * 1024;

    if (isStruct) {
        // ================= structural path: G=8, K=128 =================
        const int G = 8;
        // hoisted gather of batch 0 (hidden behind weight staging)
        float4 xr[G];
        int dr[G];
        {
            int nb = we - ws;
#pragma unroll
            for (int g = 0; g < G; g++) {
                xr[g] = make_float4(0.f, 0.f, 0.f, 0.f);
                dr[g] = 0;
                if (g < nb) {
                    int sn = g_esrc[ws + g];
                    dr[g] = g_edst[ws + g];
                    xr[g] = ((const float4*)(hs + sn * 128))[lane];
                }
            }
        }
        stage_w(sW1, g_Ws1t + t * 16384, 128, 32, threadIdx.x, 256);
        stage_w(sW2, g_Ws2t + t * 16384, 128, 32, threadIdx.x, 256);
        float b1v[4], b2v[4];
#pragma unroll
        for (int oi = 0; oi < 4; oi++) {
            b1v[oi] = bs1[t * 128 + oi * 32 + lane];
            b2v[oi] = bs2[t * 128 + oi * 32 + lane];
        }
        __syncthreads();

        for (int base = ws; base < we; base += G) {
            int ne = min(G, we - base);
            int dc[G];
#pragma unroll
            for (int g = 0; g < G; g++) {
                ((float4*)(myX + g * 128))[lane] = xr[g];
                dc[g] = dr[g];
            }
            __syncwarp();
            // prefetch next batch (hidden behind the two gemms)
            if (base + G < we) {
                int nb = we - (base + G);
#pragma unroll
                for (int g = 0; g < G; g++) {
                    xr[g] = make_float4(0.f, 0.f, 0.f, 0.f);
                    dr[g] = 0;
                    if (g < nb) {
                        int sn = g_esrc[base + G + g];
                        dr[g] = g_edst[base + G + g];
                        xr[g] = ((const float4*)(hs + sn * 128))[lane];
                    }
                }
            }
            unsigned long long a1[G][4];
            gemm_p<G, 4, 32, 32>(sW1, myX, lane, a1);
            __syncwarp();
#pragma unroll
            for (int g = 0; g < G; g++)
#pragma unroll
                for (int oi = 0; oi < 4; oi++)
                    myX[g * 128 + oi * 32 + lane] = fmaxf(unpack_sum(a1[g][oi]) + b1v[oi], 0.f);
            __syncwarp();
            unsigned long long a2[G][4];
            gemm_p<G, 4, 32, 32>(sW2, myX, lane, a2);
#pragma unroll
            for (int g = 0; g < G; g++) {
                if (g < ne) {
#pragma unroll
                    for (int oi = 0; oi < 4; oi++)
                        atomicAdd(&g_aggs[dc[g] * 128 + oi * 32 + lane],
                                  unpack_sum(a2[g][oi]) + b2v[oi]);
                }
            }
            __syncwarp();
        }
    } else {
        // ================= functional path: G=4 =================
        const int G = 4;
        bool isnot = (t == 1);
        const float *W1g, *W2g, *b1g, *b2g;
        if (isnot) {
            W1g = g_Wnf1t; W2g = g_Wnf2t; b1g = bnf1; b2g = bnf2;
        } else {
            int fi = (t == 0) ? 0 : (t == 2) ? 1 : (t == 3) ? 2 : 3;
            W1g = g_Wf1t + fi * 32768;
            W2g = g_Wf2t + fi * 16384;
            b1g = bf1 + fi * 128;
            b2g = bf2 + fi * 128;
        }
        // hoisted gather batch 0
        float4 xa[G], xb[G];
        int dr[G];
        {
            int nb = we - ws;
#pragma unroll
            for (int g = 0; g < G; g++) {
                xa[g] = make_float4(0.f, 0.f, 0.f, 0.f);
                xb[g] = xa[g];
                dr[g] = 0;
                if (g < nb) {
                    int sn = g_esrc[ws + g];
                    dr[g] = g_edst[ws + g];
                    if (isnot) {
                        xa[g] = ((const float4*)(hf + sn * 128))[lane];
                    } else {
                        xa[g] = ((const float4*)(hs + sn * 128))[lane];
                        xb[g] = ((const float4*)(hf + sn * 128))[lane];
                    }
                }
            }
        }
        stage_w(sW1, W1g, 128, isnot ? 32 : 64, threadIdx.x, 256);
        stage_w(sW2, W2g, 128, 32, threadIdx.x, 256);
        float b1v[4], b2v[4];
#pragma unroll
        for (int oi = 0; oi < 4; oi++) {
            b1v[oi] = b1g[oi * 32 + lane];
            b2v[oi] = b2g[oi * 32 + lane];
        }
        __syncthreads();

        for (int base = ws; base < we; base += G) {
            int ne = min(G, we - base);
            int dc[G];
#pragma unroll
            for (int g = 0; g < G; g++) {
                ((float4*)(myX + g * 256))[lane] = xa[g];
                ((float4*)(myX + g * 256))[32 + lane] = xb[g];
                dc[g] = dr[g];
            }
            __syncwarp();
            if (base + G < we) {
                int nb = we - (base + G);
#pragma unroll
                for (int g = 0; g < G; g++) {
                    xa[g] = make_float4(0.f, 0.f, 0.f, 0.f);
                    xb[g] = xa[g];
                    dr[g] = 0;
                    if (g < nb) {
                        int sn = g_esrc[base + G + g];
                        dr[g] = g_edst[base + G + g];
                        if (isnot) {
                            xa[g] = ((const float4*)(hf + sn * 128))[lane];
                        } else {
                            xa[g] = ((const float4*)(hs + sn * 128))[lane];
                            xb[g] = ((const float4*)(hf + sn * 128))[lane];
                        }
                    }
                }
            }
            unsigned long long a1[G][4];
            if (isnot)
                gemm_p<G, 4, 32, 64>(sW1, myX, lane, a1);
            else
                gemm_p<G, 4, 64, 64>(sW1, myX, lane, a1);
            __syncwarp();
#pragma unroll
            for (int g = 0; g < G; g++)
#pragma unroll
                for (int oi = 0; oi < 4; oi++)
                    myX[g * 256 + oi * 32 + lane] = fmaxf(unpack_sum(a1[g][oi]) + b1v[oi], 0.f);
            __syncwarp();
            unsigned long long a2[G][4];
            gemm_p<G, 4, 32, 64>(sW2, myX, lane, a2);
#pragma unroll
            for (int g = 0; g < G; g++) {
                if (g < ne) {
#pragma unroll
                    for (int oi = 0; oi < 4; oi++)
                        atomicAdd(&g_aggf[dc[g] * 128 + oi * 32 + lane],
                                  unpack_sum(a2[g][oi]) + b2v[oi]);
                }
            }
            __syncwarp();
        }
    }
}

// ---------------- GRU (h == 0), fused s/f via blockIdx.y ----------------
#define GR_NW 8
#define GR_G 4
// smem floats: 49152 + 8*4*128 = 53248 -> 212992 B
__global__ void __launch_bounds__(256, 1)
k_gru(const float* __restrict__ Gs_bih, const float* __restrict__ Gs_bhh,
      const float* __restrict__ Gf_bih, const float* __restrict__ Gf_bhh,
      float* __restrict__ hs, float* __restrict__ hf, int level) {
    extern __shared__ float sm[];
    float* sW = sm;           // [384][128] swizzled wih
    float* sX = sm + 49152;

    int t = blockIdx.y % 5;
    int isF = blockIdx.y / 5;
    int b = (level - 1) * 5 + t;
    int nS = g_noff[b], cnt = g_noff[b + 1] - nS;

    const float* agg = isF ? g_aggf : g_aggs;
    float* hout = isF ? hf : hs;
    const float* wgp = (isF ? g_Gfwih_t : g_Gswih_t) + t * 49152;
    const float* bih = (isF ? Gf_bih : Gs_bih) + t * 384;
    const float* bhh = (isF ? Gf_bhh : Gs_bhh) + t * 384;

    int w = threadIdx.x >> 5, lane = threadIdx.x & 31;
    int nw = gridDim.x * GR_NW;
    int wgi = blockIdx.x * GR_NW + w;
    int ws = nS + (int)(((long long)cnt * wgi) / nw);
    int we = nS + (int)(((long long)cnt * (wgi + 1)) / nw);
    float* myX = sX + w * GR_G * 128;

    // hoisted gather batch 0 (hidden behind 192KB weight staging)
    float4 xr[GR_G];
    int nr[GR_G];
    {
        int nb = we - ws;
#pragma unroll
        for (int g = 0; g < GR_G; g++) {
            xr[g] = make_float4(0.f, 0.f, 0.f, 0.f);
            nr[g] = 0;
            if (g < nb) {
                nr[g] = g_nodes[ws + g];
                xr[g] = ((const float4*)(agg + nr[g] * 128))[lane];
            }
        }
    }
    stage_w(sW, wgp, 384, 32, threadIdx.x, 256);
    float bR[4], bZ[4], bNi[4], bNh[4];
#pragma unroll
    for (int oi = 0; oi < 4; oi++) {
        int j = oi * 32 + lane;
        bR[oi] = bih[j] + bhh[j];
        bZ[oi] = bih[128 + j] + bhh[128 + j];
        bNi[oi] = bih[256 + j];
        bNh[oi] = bhh[256 + j];
    }
    __syncthreads();

    for (int base = ws; base < we; base += GR_G) {
        int nn = min(GR_G, we - base);
        int nc[GR_G];
#pragma unroll
        for (int g = 0; g < GR_G; g++) {
            ((float4*)(myX + g * 128))[lane] = xr[g];
            nc[g] = nr[g];
        }
        __syncwarp();
        if (base + GR_G < we) {
            int nb = we - (base + GR_G);
#pragma unroll
            for (int g = 0; g < GR_G; g++) {
                xr[g] = make_float4(0.f, 0.f, 0.f, 0.f);
                nr[g] = 0;
                if (g < nb) {
                    nr[g] = g_nodes[base + GR_G + g];
                    xr[g] = ((const float4*)(agg + nr[g] * 128))[lane];
                }
            }
        }

        unsigned long long acc[GR_G][12];
        gemm_p<GR_G, 12, 32, 32>(sW, myX, lane, acc);

#pragma unroll
        for (int g = 0; g < GR_G; g++) {
            if (g < nn) {
#pragma unroll
                for (int oi = 0; oi < 4; oi++) {
                    float r = sigmoidf_(unpack_sum(acc[g][oi]) + bR[oi]);
                    float z = sigmoidf_(unpack_sum(acc[g][oi + 4]) + bZ[oi]);
                    float n = tanhf(unpack_sum(acc[g][oi + 8]) + bNi[oi] + r * bNh[oi]);
                    hout[nc[g] * 128 + oi * 32 + lane] = (1.f - z) * n;
                }
            }
        }
        __syncwarp();
    }
}

// ---------------- host launch ----------------
extern "C" void kernel_launch(void* const* d_in, const int* in_sizes, int n_in,
                              void* d_out, int out_size) {
    const float* hs_init = (const float*)d_in[0];
    const float* Ws1 = (const float*)d_in[1];
    const float* bs1 = (const float*)d_in[2];
    const float* Ws2 = (const float*)d_in[3];
    const float* bs2 = (const float*)d_in[4];
    const float* Wf1 = (const float*)d_in[5];
    const float* bf1 = (const float*)d_in[6];
    const float* Wf2 = (const float*)d_in[7];
    const float* bf2 = (const float*)d_in[8];
    const float* Wnf1 = (const float*)d_in[9];
    const float* bnf1 = (const float*)d_in[10];
    const float* Wnf2 = (const float*)d_in[11];
    const float* bnf2 = (const float*)d_in[12];
    const float* Gs_wih = (const float*)d_in[13];
    // d_in[14] = Gs_whh (unused: h == 0)
    const float* Gs_bih = (const float*)d_in[15];
    const float* Gs_bhh = (const float*)d_in[16];
    const float* Gf_wih = (const float*)d_in[17];
    // d_in[18] = Gf_whh (unused)
    const float* Gf_bih = (const float*)d_in[19];
    const float* Gf_bhh = (const float*)d_in[20];
    const int* edge_index = (const int*)d_in[21];
    const int* gate = (const int*)d_in[22];
    const int* flev = (const int*)d_in[23];

    float* hs = (float*)d_out;
    float* hf = hs + NN * DD;

    cudaFuncSetAttribute(k_edges, cudaFuncAttributeMaxDynamicSharedMemorySize, 229376);
    cudaFuncSetAttribute(k_gru, cudaFuncAttributeMaxDynamicSharedMemorySize, 212992);

    k_init<<<1024, 256>>>(hs_init, gate, hs, hf, Ws1, Ws2, Wf1, Wf2, Wnf1, Wnf2,
                          Gs_wih, Gf_wih, edge_index, flev);
    k_scan<<<1, 1>>>();
    k_scatter<<<(EE + 255) / 256, 256>>>(edge_index, gate, flev);

    for (int level = 1; level < 5; level++) {
        k_edges<<<dim3(29, 10), 256, 229376>>>(hs, hf, bs1, bs2, bf1, bf2, bnf1, bnf2,
                                               level);
        k_gru<<<dim3(14, 10), 256, 212992>>>(Gs_bih, Gs_bhh, Gf_bih, Gf_bhh, hs, hf, level);
    }
}

// round 6
// speedup vs baseline: 1.1166x; 1.0717x over previous
#include <cuda_runtime.h>
#include <math.h>

#define NN   20000
#define DD   128
#define EE   60000
#define PERL 4000
#define NB   20   // (level-1)*5 + t, level 1..4, t 0..4

// ---------------- device scratch (no allocation allowed) ----------------
__device__ float g_aggs[NN * DD];
__device__ float g_aggf[NN * DD];
__device__ float g_Ws1t[5 * DD * DD];
__device__ float g_Ws2t[5 * DD * DD];
__device__ float g_Wf1t[4 * 2 * DD * DD];
__device__ float g_Wf2t[4 * DD * DD];
__device__ float g_Wnf1t[DD * DD];
__device__ float g_Wnf2t[DD * DD];
__device__ float g_Gswih_t[5 * 3 * DD * DD];
__device__ float g_Gfwih_t[5 * 3 * DD * DD];
__device__ int g_esrc[EE];
__device__ int g_edst[EE];
__device__ int g_ecnt[NB];   // statically zero; re-zeroed by k_scan after read
__device__ int g_eoff[NB + 1];
__device__ int g_ecur[NB];
__device__ int g_nodes[NN];
__device__ int g_ncnt[NB];
__device__ int g_noff[NB + 1];
__device__ int g_ncur[NB];

// CODES = [3,2,5,1,4] -> t index; code c in 1..5
__device__ __forceinline__ int code2t(int c) {
    switch (c) {
        case 1: return 3;
        case 2: return 1;
        case 3: return 0;
        case 4: return 4;
        default: return 2; // 5
    }
}
__device__ __forceinline__ float sigmoidf_(float x) { return 1.f / (1.f + expf(-x)); }

// packed f32x2 FMA (sm_100+): d = a*b + d on both lanes
__device__ __forceinline__ void fma2(unsigned long long& d, unsigned long long a,
                                     unsigned long long b) {
    asm("fma.rn.f32x2 %0, %1, %2, %0;" : "+l"(d) : "l"(a), "l"(b));
}
__device__ __forceinline__ float unpack_sum(unsigned long long a) {
    float lo, hi;
    asm("mov.b64 {%0, %1}, %2;" : "=f"(lo), "=f"(hi) : "l"(a));
    return lo + hi;
}

// ---------------- prep: init + count + weight transposes (fused) ----------
__device__ __forceinline__ void tr1(const float* __restrict__ src, float* __restrict__ dst,
                                    int idx, int K, int J) {
    int m = idx / (K * J);
    int r = idx - m * (K * J);
    int k = r / J;
    int j = r - k * J;
    dst[m * K * J + j * K + k] = src[idx];
}

#define INIT_TOTAL (NN * DD)
#define PREP_TOTAL 884736
__global__ void k_init(const float* __restrict__ hs_init, const int* __restrict__ gate,
                       float* __restrict__ hs, float* __restrict__ hf,
                       const float* __restrict__ Ws1, const float* __restrict__ Ws2,
                       const float* __restrict__ Wf1, const float* __restrict__ Wf2,
                       const float* __restrict__ Wnf1, const float* __restrict__ Wnf2,
                       const float* __restrict__ Gs, const float* __restrict__ Gf,
                       const int* __restrict__ ei, const int* __restrict__ flev) {
    int stride = gridDim.x * blockDim.x;
    int tid0 = blockIdx.x * blockDim.x + threadIdx.x;
    // counting pass (g_ecnt/g_ncnt are zero: static init on call 0, k_scan re-zeroes after)
    {
        int i = tid0;
        if (i < EE) {
            int dst = ei[EE + i];
            int b = (flev[dst] - 1) * 5 + code2t(gate[dst]);
            atomicAdd(&g_ecnt[b], 1);
        }
        int v = i + PERL;
        if (i < NN - PERL) {
            int b = (flev[v] - 1) * 5 + code2t(gate[v]);
            atomicAdd(&g_ncnt[b], 1);
        }
    }
    for (int i = tid0; i < INIT_TOTAL; i += stride) {
        int v = i >> 7;
        hs[i] = (gate[v] == 0) ? hs_init[i] : 0.f;
        hf[i] = 0.f;
        g_aggs[i] = 0.f;
        g_aggf[i] = 0.f;
    }
    for (int i = tid0; i < PREP_TOTAL; i += stride) {
        int idx = i;
        if (idx < 81920) { tr1(Ws1, g_Ws1t, idx, 128, 128); continue; }
        idx -= 81920;
        if (idx < 81920) { tr1(Ws2, g_Ws2t, idx, 128, 128); continue; }
        idx -= 81920;
        if (idx < 131072) { tr1(Wf1, g_Wf1t, idx, 256, 128); continue; }
        idx -= 131072;
        if (idx < 65536) { tr1(Wf2, g_Wf2t, idx, 128, 128); continue; }
        idx -= 65536;
        if (idx < 16384) { tr1(Wnf1, g_Wnf1t, idx, 128, 128); continue; }
        idx -= 16384;
        if (idx < 16384) { tr1(Wnf2, g_Wnf2t, idx, 128, 128); continue; }
        idx -= 16384;
        if (idx < 245760) { tr1(Gs, g_Gswih_t, idx, 128, 384); continue; }
        idx -= 245760;
        tr1(Gf, g_Gfwih_t, idx, 128, 384);
    }
}

__global__ void k_scan() {
    if (threadIdx.x == 0 && blockIdx.x == 0) {
        int s = 0, t = 0;
        for (int b = 0; b < NB; b++) {
            g_eoff[b] = s; g_ecur[b] = s; s += g_ecnt[b];
            g_noff[b] = t; g_ncur[b] = t; t += g_ncnt[b];
            g_ecnt[b] = 0;  // re-zero for next graph replay (deterministic)
            g_ncnt[b] = 0;
        }
        g_eoff[NB] = s;
        g_noff[NB] = t;
    }
}

__global__ void k_scatter(const int* __restrict__ ei, const int* __restrict__ gate,
                          const int* __restrict__ flev) {
    int i = blockIdx.x * blockDim.x + threadIdx.x;
    if (i < EE) {
        int src = ei[i], dst = ei[EE + i];
        int b = (flev[dst] - 1) * 5 + code2t(gate[dst]);
        int p = atomicAdd(&g_ecur[b], 1);
        g_esrc[p] = src;
        g_edst[p] = dst;
    }
    int v = i + PERL;
    if (i < NN - PERL) {
        int b = (flev[v] - 1) * 5 + code2t(gate[v]);
        int p = atomicAdd(&g_ncur[b], 1);
        g_nodes[p] = v;
    }
}

// stage transposed weights into smem; f4 slot c in row goes to c ^ (row & 7).
__device__ __forceinline__ void stage_w(float* __restrict__ dst, const float* __restrict__ src,
                                        int rows, int k4n, int tid, int nthr) {
    float4* d = (float4*)dst;
    const float4* sp = (const float4*)src;
    int tot = rows * k4n;
    for (int i = tid; i < tot; i += nthr) {
        int row = i / k4n;
        int c = i - row * k4n;
        d[row * k4n + (c ^ (row & 7))] = sp[i];
    }
}

// ---------------- packed-FMA warp GEMM (compile-time K) ----------------
// sW swizzled [NOUT*32 rows][K4N 16B-chunks]; lane owns output rows oi*32+lane.
// sX unswizzled, G rows of XS4 chunks; broadcast reads.
template <int G, int NOUT, int K4N, int XS4>
__device__ __forceinline__ void gemm_p(const float* __restrict__ sW,
                                       const float* __restrict__ sX, int lane,
                                       unsigned long long (&acc)[G][NOUT]) {
    const ulonglong2* wU = (const ulonglong2*)sW;
    const ulonglong2* xU = (const ulonglong2*)sX;
    int s = lane & 7;
#pragma unroll
    for (int g = 0; g < G; g++)
#pragma unroll
        for (int oi = 0; oi < NOUT; oi++) acc[g][oi] = 0ull;
#pragma unroll 8
    for (int k4 = 0; k4 < K4N; k4++) {
        int kk = k4 ^ s;
        ulonglong2 xv[G];
#pragma unroll
        for (int g = 0; g < G; g++) xv[g] = xU[g * XS4 + k4];
#pragma unroll
        for (int oi = 0; oi < NOUT; oi++) {
            ulonglong2 wv = wU[(oi * 32 + lane) * K4N + kk];
#pragma unroll
            for (int g = 0; g < G; g++) {
                fma2(acc[g][oi], xv[g].x, wv.x);
                fma2(acc[g][oi], xv[g].y, wv.y);
            }
        }
    }
}

// ---------------- fused edge kernel, work-weighted 1D grid ----------------
// 144 blocks: struct t=0..4 get 12 each [0,60); func: and 18, not 12, xor 18,
// maj 18, or 18 -> [60,144). One wave on 148 SMs.
#define E_NW 8
#define E_GRID 144
// smem floats: 32768(sW1) + 16384(sW2) + 8*1024(sX) = 57344 -> 229376 B
__global__ void __launch_bounds__(256, 1)
k_edges(const float* __restrict__ hs, const float* __restrict__ hf,
        const float* __restrict__ bs1, const float* __restrict__ bs2,
        const float* __restrict__ bf1, const float* __restrict__ bf2,
        const float* __restrict__ bnf1, const float* __restrict__ bnf2, int level) {
    extern __shared__ float sm[];
    float* sW1 = sm;
    float* sW2 = sm + 32768;
    float* sX = sm + 49152;

    int bid = blockIdx.x;
    bool isStruct;
    int t, seg, nseg;
    if (bid < 60) {
        isStruct = true;
        t = bid / 12; seg = bid - t * 12; nseg = 12;
    } else {
        isStruct = false;
        int r = bid - 60;
        if (r < 18)      { t = 0; seg = r;      nseg = 18; }
        else if (r < 30) { t = 1; seg = r - 18; nseg = 12; }
        else if (r < 48) { t = 2; seg = r - 30; nseg = 18; }
        else if (r < 66) { t = 3; seg = r - 48; nseg = 18; }
        else             { t = 4; seg = r - 66; nseg = 18; }
    }
    int b = (level - 1) * 5 + t;
    int eS = g_eoff[b], cnt = g_eoff[b + 1] - eS;

    int w = threadIdx.x >> 5, lane = threadIdx.x & 31;
    int nw = nseg * E_NW;
    int wgi = seg * E_NW + w;
    int ws = eS + (int)(((long long)cnt * wgi) / nw);
    int we = eS + (int)(((long long)cnt * (wgi + 1)) / nw);
    float* myX = sX + w * 1024;

    if (isStruct) {
        // ================= structural path: G=8, K=128 =================
        const int G = 8;
        float4 xr[G];
        int dr[G];
        {
            int nb = we - ws;
#pragma unroll
            for (int g = 0; g < G; g++) {
                xr[g] = make_float4(0.f, 0.f, 0.f, 0.f);
                dr[g] = 0;
                if (g < nb) {
                    int sn = g_esrc[ws + g];
                    dr[g] = g_edst[ws + g];
                    xr[g] = ((const float4*)(hs + sn * 128))[lane];
                }
            }
        }
        stage_w(sW1, g_Ws1t + t * 16384, 128, 32, threadIdx.x, 256);
        stage_w(sW2, g_Ws2t + t * 16384, 128, 32, threadIdx.x, 256);
        float b1v[4], b2v[4];
#pragma unroll
        for (int oi = 0; oi < 4; oi++) {
            b1v[oi] = bs1[t * 128 + oi * 32 + lane];
            b2v[oi] = bs2[t * 128 + oi * 32 + lane];
        }
        __syncthreads();

        for (int base = ws; base < we; base += G) {
            int ne = min(G, we - base);
            int dc[G];
#pragma unroll
            for (int g = 0; g < G; g++) {
                ((float4*)(myX + g * 128))[lane] = xr[g];
                dc[g] = dr[g];
            }
            __syncwarp();
            if (base + G < we) {
                int nb = we - (base + G);
#pragma unroll
                for (int g = 0; g < G; g++) {
                    xr[g] = make_float4(0.f, 0.f, 0.f, 0.f);
                    dr[g] = 0;
                    if (g < nb) {
                        int sn = g_esrc[base + G + g];
                        dr[g] = g_edst[base + G + g];
                        xr[g] = ((const float4*)(hs + sn * 128))[lane];
                    }
                }
            }
            unsigned long long a1[G][4];
            gemm_p<G, 4, 32, 32>(sW1, myX, lane, a1);
            __syncwarp();
#pragma unroll
            for (int g = 0; g < G; g++)
#pragma unroll
                for (int oi = 0; oi < 4; oi++)
                    myX[g * 128 + oi * 32 + lane] = fmaxf(unpack_sum(a1[g][oi]) + b1v[oi], 0.f);
            __syncwarp();
            unsigned long long a2[G][4];
            gemm_p<G, 4, 32, 32>(sW2, myX, lane, a2);
#pragma unroll
            for (int g = 0; g < G; g++) {
                if (g < ne) {
#pragma unroll
                    for (int oi = 0; oi < 4; oi++)
                        atomicAdd(&g_aggs[dc[g] * 128 + oi * 32 + lane],
                                  unpack_sum(a2[g][oi]) + b2v[oi]);
                }
            }
            __syncwarp();
        }
    } else {
        // ================= functional path: G=4 =================
        const int G = 4;
        bool isnot = (t == 1);
        const float *W1g, *W2g, *b1g, *b2g;
        if (isnot) {
            W1g = g_Wnf1t; W2g = g_Wnf2t; b1g = bnf1; b2g = bnf2;
        } else {
            int fi = (t == 0) ? 0 : (t == 2) ? 1 : (t == 3) ? 2 : 3;
            W1g = g_Wf1t + fi * 32768;
            W2g = g_Wf2t + fi * 16384;
            b1g = bf1 + fi * 128;
            b2g = bf2 + fi * 128;
        }
        float4 xa[G], xb[G];
        int dr[G];
        {
            int nb = we - ws;
#pragma unroll
            for (int g = 0; g < G; g++) {
                xa[g] = make_float4(0.f, 0.f, 0.f, 0.f);
                xb[g] = xa[g];
                dr[g] = 0;
                if (g < nb) {
                    int sn = g_esrc[ws + g];
                    dr[g] = g_edst[ws + g];
                    if (isnot) {
                        xa[g] = ((const float4*)(hf + sn * 128))[lane];
                    } else {
                        xa[g] = ((const float4*)(hs + sn * 128))[lane];
                        xb[g] = ((const float4*)(hf + sn * 128))[lane];
                    }
                }
            }
        }
        stage_w(sW1, W1g, 128, isnot ? 32 : 64, threadIdx.x, 256);
        stage_w(sW2, W2g, 128, 32, threadIdx.x, 256);
        float b1v[4], b2v[4];
#pragma unroll
        for (int oi = 0; oi < 4; oi++) {
            b1v[oi] = b1g[oi * 32 + lane];
            b2v[oi] = b2g[oi * 32 + lane];
        }
        __syncthreads();

        for (int base = ws; base < we; base += G) {
            int ne = min(G, we - base);
            int dc[G];
#pragma unroll
            for (int g = 0; g < G; g++) {
                ((float4*)(myX + g * 256))[lane] = xa[g];
                ((float4*)(myX + g * 256))[32 + lane] = xb[g];
                dc[g] = dr[g];
            }
            __syncwarp();
            if (base + G < we) {
                int nb = we - (base + G);
#pragma unroll
                for (int g = 0; g < G; g++) {
                    xa[g] = make_float4(0.f, 0.f, 0.f, 0.f);
                    xb[g] = xa[g];
                    dr[g] = 0;
                    if (g < nb) {
                        int sn = g_esrc[base + G + g];
                        dr[g] = g_edst[base + G + g];
                        if (isnot) {
                            xa[g] = ((const float4*)(hf + sn * 128))[lane];
                        } else {
                            xa[g] = ((const float4*)(hs + sn * 128))[lane];
                            xb[g] = ((const float4*)(hf + sn * 128))[lane];
                        }
                    }
                }
            }
            unsigned long long a1[G][4];
            if (isnot)
                gemm_p<G, 4, 32, 64>(sW1, myX, lane, a1);
            else
                gemm_p<G, 4, 64, 64>(sW1, myX, lane, a1);
            __syncwarp();
#pragma unroll
            for (int g = 0; g < G; g++)
#pragma unroll
                for (int oi = 0; oi < 4; oi++)
                    myX[g * 256 + oi * 32 + lane] = fmaxf(unpack_sum(a1[g][oi]) + b1v[oi], 0.f);
            __syncwarp();
            unsigned long long a2[G][4];
            gemm_p<G, 4, 32, 64>(sW2, myX, lane, a2);
#pragma unroll
            for (int g = 0; g < G; g++) {
                if (g < ne) {
#pragma unroll
                    for (int oi = 0; oi < 4; oi++)
                        atomicAdd(&g_aggf[dc[g] * 128 + oi * 32 + lane],
                                  unpack_sum(a2[g][oi]) + b2v[oi]);
                }
            }
            __syncwarp();
        }
    }
}

// ---------------- GRU (h == 0), fused s/f via blockIdx.y ----------------
#define GR_NW 8
#define GR_G 4
// smem floats: 49152 + 8*4*128 = 53248 -> 212992 B
__global__ void __launch_bounds__(256, 1)
k_gru(const float* __restrict__ Gs_bih, const float* __restrict__ Gs_bhh,
      const float* __restrict__ Gf_bih, const float* __restrict__ Gf_bhh,
      float* __restrict__ hs, float* __restrict__ hf, int level) {
    extern __shared__ float sm[];
    float* sW = sm;           // [384][128] swizzled wih
    float* sX = sm + 49152;

    int t = blockIdx.y % 5;
    int isF = blockIdx.y / 5;
    int b = (level - 1) * 5 + t;
    int nS = g_noff[b], cnt = g_noff[b + 1] - nS;

    const float* agg = isF ? g_aggf : g_aggs;
    float* hout = isF ? hf : hs;
    const float* wgp = (isF ? g_Gfwih_t : g_Gswih_t) + t * 49152;
    const float* bih = (isF ? Gf_bih : Gs_bih) + t * 384;
    const float* bhh = (isF ? Gf_bhh : Gs_bhh) + t * 384;

    int w = threadIdx.x >> 5, lane = threadIdx.x & 31;
    int nw = gridDim.x * GR_NW;
    int wgi = blockIdx.x * GR_NW + w;
    int ws = nS + (int)(((long long)cnt * wgi) / nw);
    int we = nS + (int)(((long long)cnt * (wgi + 1)) / nw);
    float* myX = sX + w * GR_G * 128;

    float4 xr[GR_G];
    int nr[GR_G];
    {
        int nb = we - ws;
#pragma unroll
        for (int g = 0; g < GR_G; g++) {
            xr[g] = make_float4(0.f, 0.f, 0.f, 0.f);
            nr[g] = 0;
            if (g < nb) {
                nr[g] = g_nodes[ws + g];
                xr[g] = ((const float4*)(agg + nr[g] * 128))[lane];
            }
        }
    }
    stage_w(sW, wgp, 384, 32, threadIdx.x, 256);
    float bR[4], bZ[4], bNi[4], bNh[4];
#pragma unroll
    for (int oi = 0; oi < 4; oi++) {
        int j = oi * 32 + lane;
        bR[oi] = bih[j] + bhh[j];
        bZ[oi] = bih[128 + j] + bhh[128 + j];
        bNi[oi] = bih[256 + j];
        bNh[oi] = bhh[256 + j];
    }
    __syncthreads();

    for (int base = ws; base < we; base += GR_G) {
        int nn = min(GR_G, we - base);
        int nc[GR_G];
#pragma unroll
        for (int g = 0; g < GR_G; g++) {
            ((float4*)(myX + g * 128))[lane] = xr[g];
            nc[g] = nr[g];
        }
        __syncwarp();
        if (base + GR_G < we) {
            int nb = we - (base + GR_G);
#pragma unroll
            for (int g = 0; g < GR_G; g++) {
                xr[g] = make_float4(0.f, 0.f, 0.f, 0.f);
                nr[g] = 0;
                if (g < nb) {
                    nr[g] = g_nodes[base + GR_G + g];
                    xr[g] = ((const float4*)(agg + nr[g] * 128))[lane];
                }
            }
        }

        unsigned long long acc[GR_G][12];
        gemm_p<GR_G, 12, 32, 32>(sW, myX, lane, acc);

#pragma unroll
        for (int g = 0; g < GR_G; g++) {
            if (g < nn) {
#pragma unroll
                for (int oi = 0; oi < 4; oi++) {
                    float r = sigmoidf_(unpack_sum(acc[g][oi]) + bR[oi]);
                    float z = sigmoidf_(unpack_sum(acc[g][oi + 4]) + bZ[oi]);
                    float n = tanhf(unpack_sum(acc[g][oi + 8]) + bNi[oi] + r * bNh[oi]);
                    hout[nc[g] * 128 + oi * 32 + lane] = (1.f - z) * n;
                }
            }
        }
        __syncwarp();
    }
}

// ---------------- host launch ----------------
extern "C" void kernel_launch(void* const* d_in, const int* in_sizes, int n_in,
                              void* d_out, int out_size) {
    const float* hs_init = (const float*)d_in[0];
    const float* Ws1 = (const float*)d_in[1];
    const float* bs1 = (const float*)d_in[2];
    const float* Ws2 = (const float*)d_in[3];
    const float* bs2 = (const float*)d_in[4];
    const float* Wf1 = (const float*)d_in[5];
    const float* bf1 = (const float*)d_in[6];
    const float* Wf2 = (const float*)d_in[7];
    const float* bf2 = (const float*)d_in[8];
    const float* Wnf1 = (const float*)d_in[9];
    const float* bnf1 = (const float*)d_in[10];
    const float* Wnf2 = (const float*)d_in[11];
    const float* bnf2 = (const float*)d_in[12];
    const float* Gs_wih = (const float*)d_in[13];
    // d_in[14] = Gs_whh (unused: h == 0)
    const float* Gs_bih = (const float*)d_in[15];
    const float* Gs_bhh = (const float*)d_in[16];
    const float* Gf_wih = (const float*)d_in[17];
    // d_in[18] = Gf_whh (unused)
    const float* Gf_bih = (const float*)d_in[19];
    const float* Gf_bhh = (const float*)d_in[20];
    const int* edge_index = (const int*)d_in[21];
    const int* gate = (const int*)d_in[22];
    const int* flev = (const int*)d_in[23];

    float* hs = (float*)d_out;
    float* hf = hs + NN * DD;

    cudaFuncSetAttribute(k_edges, cudaFuncAttributeMaxDynamicSharedMemorySize, 229376);
    cudaFuncSetAttribute(k_gru, cudaFuncAttributeMaxDynamicSharedMemorySize, 212992);

    k_init<<<1024, 256>>>(hs_init, gate, hs, hf, Ws1, Ws2, Wf1, Wf2, Wnf1, Wnf2,
                          Gs_wih, Gf_wih, edge_index, flev);
    k_scan<<<1, 1>>>();
    k_scatter<<<(EE + 255) / 256, 256>>>(edge_index, gate, flev);

    for (int level = 1; level < 5; level++) {
        k_edges<<<E_GRID, 256, 229376>>>(hs, hf, bs1, bs2, bf1, bf2, bnf1, bnf2, level);
        k_gru<<<dim3(14, 10), 256, 212992>>>(Gs_bih, Gs_bhh, Gf_bih, Gf_bhh, hs, hf, level);
    }
}

// round 7
// speedup vs baseline: 1.1343x; 1.0159x over previous
#include <cuda_runtime.h>
#include <math.h>

#define NN   20000
#define DD   128
#define EE   60000
#define PERL 4000
#define NB   20   // (level-1)*5 + t, level 1..4, t 0..4

// ---------------- device scratch (no allocation allowed) ----------------
__device__ float g_aggs[NN * DD];
__device__ float g_aggf[NN * DD];
__device__ float g_Ws1t[5 * DD * DD];
__device__ float g_Ws2t[5 * DD * DD];
__device__ float g_Wf1t[4 * 2 * DD * DD];
__device__ float g_Wf2t[4 * DD * DD];
__device__ float g_Wnf1t[DD * DD];
__device__ float g_Wnf2t[DD * DD];
__device__ float g_Gswih_t[5 * 3 * DD * DD];
__device__ float g_Gfwih_t[5 * 3 * DD * DD];
__device__ int g_esrc[EE];
__device__ int g_edst[EE];
__device__ int g_ecnt[NB];   // statically zero; re-zeroed by k_scan after read
__device__ int g_eoff[NB + 1];
__device__ int g_ecur[NB];
__device__ int g_nodes[NN];
__device__ int g_ncnt[NB];
__device__ int g_noff[NB + 1];
__device__ int g_ncur[NB];

// CODES = [3,2,5,1,4] -> t index; code c in 1..5
__device__ __forceinline__ int code2t(int c) {
    switch (c) {
        case 1: return 3;
        case 2: return 1;
        case 3: return 0;
        case 4: return 4;
        default: return 2; // 5
    }
}
__device__ __forceinline__ float sigmoidf_(float x) { return 1.f / (1.f + expf(-x)); }

// packed f32x2 FMA (sm_100+): d = a*b + d on both lanes
__device__ __forceinline__ void fma2(unsigned long long& d, unsigned long long a,
                                     unsigned long long b) {
    asm("fma.rn.f32x2 %0, %1, %2, %0;" : "+l"(d) : "l"(a), "l"(b));
}
__device__ __forceinline__ float unpack_sum(unsigned long long a) {
    float lo, hi;
    asm("mov.b64 {%0, %1}, %2;" : "=f"(lo), "=f"(hi) : "l"(a));
    return lo + hi;
}

// ---------------- prep: init + count + weight transposes (fused) ----------
__device__ __forceinline__ void tr1(const float* __restrict__ src, float* __restrict__ dst,
                                    int idx, int K, int J) {
    int m = idx / (K * J);
    int r = idx - m * (K * J);
    int k = r / J;
    int j = r - k * J;
    dst[m * K * J + j * K + k] = src[idx];
}

#define INIT_TOTAL (NN * DD)
#define PREP_TOTAL 884736
__global__ void k_init(const float* __restrict__ hs_init, const int* __restrict__ gate,
                       float* __restrict__ hs, float* __restrict__ hf,
                       const float* __restrict__ Ws1, const float* __restrict__ Ws2,
                       const float* __restrict__ Wf1, const float* __restrict__ Wf2,
                       const float* __restrict__ Wnf1, const float* __restrict__ Wnf2,
                       const float* __restrict__ Gs, const float* __restrict__ Gf,
                       const int* __restrict__ ei, const int* __restrict__ flev) {
    int stride = gridDim.x * blockDim.x;
    int tid0 = blockIdx.x * blockDim.x + threadIdx.x;
    // counting pass (g_ecnt/g_ncnt are zero: static init on call 0, k_scan re-zeroes after)
    {
        int i = tid0;
        if (i < EE) {
            int dst = ei[EE + i];
            int b = (flev[dst] - 1) * 5 + code2t(gate[dst]);
            atomicAdd(&g_ecnt[b], 1);
        }
        int v = i + PERL;
        if (i < NN - PERL) {
            int b = (flev[v] - 1) * 5 + code2t(gate[v]);
            atomicAdd(&g_ncnt[b], 1);
        }
    }
    for (int i = tid0; i < INIT_TOTAL; i += stride) {
        int v = i >> 7;
        hs[i] = (gate[v] == 0) ? hs_init[i] : 0.f;
        hf[i] = 0.f;
        g_aggs[i] = 0.f;
        g_aggf[i] = 0.f;
    }
    for (int i = tid0; i < PREP_TOTAL; i += stride) {
        int idx = i;
        if (idx < 81920) { tr1(Ws1, g_Ws1t, idx, 128, 128); continue; }
        idx -= 81920;
        if (idx < 81920) { tr1(Ws2, g_Ws2t, idx, 128, 128); continue; }
        idx -= 81920;
        if (idx < 131072) { tr1(Wf1, g_Wf1t, idx, 256, 128); continue; }
        idx -= 131072;
        if (idx < 65536) { tr1(Wf2, g_Wf2t, idx, 128, 128); continue; }
        idx -= 65536;
        if (idx < 16384) { tr1(Wnf1, g_Wnf1t, idx, 128, 128); continue; }
        idx -= 16384;
        if (idx < 16384) { tr1(Wnf2, g_Wnf2t, idx, 128, 128); continue; }
        idx -= 16384;
        if (idx < 245760) { tr1(Gs, g_Gswih_t, idx, 128, 384); continue; }
        idx -= 245760;
        tr1(Gf, g_Gfwih_t, idx, 128, 384);
    }
}

__global__ void k_scan() {
    if (threadIdx.x == 0 && blockIdx.x == 0) {
        int s = 0, t = 0;
        for (int b = 0; b < NB; b++) {
            g_eoff[b] = s; g_ecur[b] = s; s += g_ecnt[b];
            g_noff[b] = t; g_ncur[b] = t; t += g_ncnt[b];
            g_ecnt[b] = 0;  // re-zero for next graph replay (deterministic)
            g_ncnt[b] = 0;
        }
        g_eoff[NB] = s;
        g_noff[NB] = t;
    }
}

__global__ void k_scatter(const int* __restrict__ ei, const int* __restrict__ gate,
                          const int* __restrict__ flev) {
    int i = blockIdx.x * blockDim.x + threadIdx.x;
    if (i < EE) {
        int src = ei[i], dst = ei[EE + i];
        int b = (flev[dst] - 1) * 5 + code2t(gate[dst]);
        int p = atomicAdd(&g_ecur[b], 1);
        g_esrc[p] = src;
        g_edst[p] = dst;
    }
    int v = i + PERL;
    if (i < NN - PERL) {
        int b = (flev[v] - 1) * 5 + code2t(gate[v]);
        int p = atomicAdd(&g_ncur[b], 1);
        g_nodes[p] = v;
    }
}

// stage transposed weights into smem with vec-lane row permutation + XOR swizzle.
// staged row r (within 128-row block gb) holds SOURCE row gb*128 + 4*(r&31) + (r>>5 & 3),
// so gemm's lane computes outputs j = lane*4 + oi (contiguous per lane -> float4 I/O).
// f4 chunk c within staged row goes to slot c ^ (r & 7) (conflict-free LDS.128).
__device__ __forceinline__ void stage_w_vec(float* __restrict__ dst,
                                            const float* __restrict__ src,
                                            int nblk, int k4n, int tid, int nthr) {
    float4* d = (float4*)dst;
    const float4* sp = (const float4*)src;
    int tot = nblk * 128 * k4n;
    for (int i = tid; i < tot; i += nthr) {
        int r = i / k4n;         // staged row index
        int c = i - r * k4n;
        int gb = r >> 7;
        int rr = r & 127;
        int lane = rr & 31, oi = rr >> 5;
        int srow = (gb << 7) + lane * 4 + oi;
        d[r * k4n + (c ^ (r & 7))] = sp[srow * k4n + c];
    }
}

// ---------------- packed-FMA warp GEMM (compile-time K) ----------------
// sW staged as above; lane's acc[g][oi] = output j = lane*4+oi.
// sX unswizzled, G rows of XS4 chunks; broadcast reads.
template <int G, int NOUT, int K4N, int XS4>
__device__ __forceinline__ void gemm_p(const float* __restrict__ sW,
                                       const float* __restrict__ sX, int lane,
                                       unsigned long long (&acc)[G][NOUT]) {
    const ulonglong2* wU = (const ulonglong2*)sW;
    const ulonglong2* xU = (const ulonglong2*)sX;
    int s = lane & 7;
#pragma unroll
    for (int g = 0; g < G; g++)
#pragma unroll
        for (int oi = 0; oi < NOUT; oi++) acc[g][oi] = 0ull;
#pragma unroll 8
    for (int k4 = 0; k4 < K4N; k4++) {
        int kk = k4 ^ s;
        ulonglong2 xv[G];
#pragma unroll
        for (int g = 0; g < G; g++) xv[g] = xU[g * XS4 + k4];
#pragma unroll
        for (int oi = 0; oi < NOUT; oi++) {
            ulonglong2 wv = wU[(oi * 32 + lane) * K4N + kk];
#pragma unroll
            for (int g = 0; g < G; g++) {
                fma2(acc[g][oi], xv[g].x, wv.x);
                fma2(acc[g][oi], xv[g].y, wv.y);
            }
        }
    }
}

// ---------------- fused edge kernel, work-weighted 1D grid ----------------
// 144 blocks: struct t=0..4 get 12 each [0,60); func: and 18, not 12, xor 18,
// maj 18, or 18 -> [60,144). One wave on 148 SMs.
#define E_NW 8
#define E_GRID 144
// smem floats: 32768(sW1) + 16384(sW2) + 8*1024(sX) = 57344 -> 229376 B
__global__ void __launch_bounds__(256, 1)
k_edges(const float* __restrict__ hs, const float* __restrict__ hf,
        const float* __restrict__ bs1, const float* __restrict__ bs2,
        const float* __restrict__ bf1, const float* __restrict__ bf2,
        const float* __restrict__ bnf1, const float* __restrict__ bnf2, int level) {
    extern __shared__ float sm[];
    float* sW1 = sm;
    float* sW2 = sm + 32768;
    float* sX = sm + 49152;

    int bid = blockIdx.x;
    bool isStruct;
    int t, seg, nseg;
    if (bid < 60) {
        isStruct = true;
        t = bid / 12; seg = bid - t * 12; nseg = 12;
    } else {
        isStruct = false;
        int r = bid - 60;
        if (r < 18)      { t = 0; seg = r;      nseg = 18; }
        else if (r < 30) { t = 1; seg = r - 18; nseg = 12; }
        else if (r < 48) { t = 2; seg = r - 30; nseg = 18; }
        else if (r < 66) { t = 3; seg = r - 48; nseg = 18; }
        else             { t = 4; seg = r - 66; nseg = 18; }
    }
    int b = (level - 1) * 5 + t;
    int eS = g_eoff[b], cnt = g_eoff[b + 1] - eS;

    int w = threadIdx.x >> 5, lane = threadIdx.x & 31;
    int nw = nseg * E_NW;
    int wgi = seg * E_NW + w;
    int ws = eS + (int)(((long long)cnt * wgi) / nw);
    int we = eS + (int)(((long long)cnt * (wgi + 1)) / nw);
    float* myX = sX + w * 1024;

    if (isStruct) {
        // ================= structural path: G=8, K=128 =================
        const int G = 8;
        float4 xr[G];
        int dr[G];
        {
            int nb = we - ws;
#pragma unroll
            for (int g = 0; g < G; g++) {
                xr[g] = make_float4(0.f, 0.f, 0.f, 0.f);
                dr[g] = 0;
                if (g < nb) {
                    int sn = g_esrc[ws + g];
                    dr[g] = g_edst[ws + g];
                    xr[g] = ((const float4*)(hs + sn * 128))[lane];
                }
            }
        }
        stage_w_vec(sW1, g_Ws1t + t * 16384, 1, 32, threadIdx.x, 256);
        stage_w_vec(sW2, g_Ws2t + t * 16384, 1, 32, threadIdx.x, 256);
        float4 b1v = ((const float4*)(bs1 + t * 128))[lane];
        float4 b2v = ((const float4*)(bs2 + t * 128))[lane];
        __syncthreads();

        for (int base = ws; base < we; base += G) {
            int ne = min(G, we - base);
            int dc[G];
#pragma unroll
            for (int g = 0; g < G; g++) {
                ((float4*)(myX + g * 128))[lane] = xr[g];
                dc[g] = dr[g];
            }
            __syncwarp();
            if (base + G < we) {
                int nb = we - (base + G);
#pragma unroll
                for (int g = 0; g < G; g++) {
                    xr[g] = make_float4(0.f, 0.f, 0.f, 0.f);
                    dr[g] = 0;
                    if (g < nb) {
                        int sn = g_esrc[base + G + g];
                        dr[g] = g_edst[base + G + g];
                        xr[g] = ((const float4*)(hs + sn * 128))[lane];
                    }
                }
            }
            unsigned long long a1[G][4];
            gemm_p<G, 4, 32, 32>(sW1, myX, lane, a1);
            __syncwarp();
#pragma unroll
            for (int g = 0; g < G; g++) {
                float4 y = make_float4(fmaxf(unpack_sum(a1[g][0]) + b1v.x, 0.f),
                                       fmaxf(unpack_sum(a1[g][1]) + b1v.y, 0.f),
                                       fmaxf(unpack_sum(a1[g][2]) + b1v.z, 0.f),
                                       fmaxf(unpack_sum(a1[g][3]) + b1v.w, 0.f));
                ((float4*)(myX + g * 128))[lane] = y;
            }
            __syncwarp();
            unsigned long long a2[G][4];
            gemm_p<G, 4, 32, 32>(sW2, myX, lane, a2);
#pragma unroll
            for (int g = 0; g < G; g++) {
                if (g < ne) {
                    float4 v = make_float4(unpack_sum(a2[g][0]) + b2v.x,
                                           unpack_sum(a2[g][1]) + b2v.y,
                                           unpack_sum(a2[g][2]) + b2v.z,
                                           unpack_sum(a2[g][3]) + b2v.w);
                    atomicAdd((float4*)&g_aggs[dc[g] * 128 + lane * 4], v);
                }
            }
            __syncwarp();
        }
    } else {
        // ================= functional path: G=4 =================
        const int G = 4;
        bool isnot = (t == 1);
        const float *W1g, *W2g, *b1g, *b2g;
        if (isnot) {
            W1g = g_Wnf1t; W2g = g_Wnf2t; b1g = bnf1; b2g = bnf2;
        } else {
            int fi = (t == 0) ? 0 : (t == 2) ? 1 : (t == 3) ? 2 : 3;
            W1g = g_Wf1t + fi * 32768;
            W2g = g_Wf2t + fi * 16384;
            b1g = bf1 + fi * 128;
            b2g = bf2 + fi * 128;
        }
        float4 xa[G], xb[G];
        int dr[G];
        {
            int nb = we - ws;
#pragma unroll
            for (int g = 0; g < G; g++) {
                xa[g] = make_float4(0.f, 0.f, 0.f, 0.f);
                xb[g] = xa[g];
                dr[g] = 0;
                if (g < nb) {
                    int sn = g_esrc[ws + g];
                    dr[g] = g_edst[ws + g];
                    if (isnot) {
                        xa[g] = ((const float4*)(hf + sn * 128))[lane];
                    } else {
                        xa[g] = ((const float4*)(hs + sn * 128))[lane];
                        xb[g] = ((const float4*)(hf + sn * 128))[lane];
                    }
                }
            }
        }
        stage_w_vec(sW1, W1g, 1, isnot ? 32 : 64, threadIdx.x, 256);
        stage_w_vec(sW2, W2g, 1, 32, threadIdx.x, 256);
        float4 b1v = ((const float4*)b1g)[lane];
        float4 b2v = ((const float4*)b2g)[lane];
        __syncthreads();

        for (int base = ws; base < we; base += G) {
            int ne = min(G, we - base);
            int dc[G];
#pragma unroll
            for (int g = 0; g < G; g++) {
                ((float4*)(myX + g * 256))[lane] = xa[g];
                ((float4*)(myX + g * 256))[32 + lane] = xb[g];
                dc[g] = dr[g];
            }
            __syncwarp();
            if (base + G < we) {
                int nb = we - (base + G);
#pragma unroll
                for (int g = 0; g < G; g++) {
                    xa[g] = make_float4(0.f, 0.f, 0.f, 0.f);
                    xb[g] = xa[g];
                    dr[g] = 0;
                    if (g < nb) {
                        int sn = g_esrc[base + G + g];
                        dr[g] = g_edst[base + G + g];
                        if (isnot) {
                            xa[g] = ((const float4*)(hf + sn * 128))[lane];
                        } else {
                            xa[g] = ((const float4*)(hs + sn * 128))[lane];
                            xb[g] = ((const float4*)(hf + sn * 128))[lane];
                        }
                    }
                }
            }
            unsigned long long a1[G][4];
            if (isnot)
                gemm_p<G, 4, 32, 64>(sW1, myX, lane, a1);
            else
                gemm_p<G, 4, 64, 64>(sW1, myX, lane, a1);
            __syncwarp();
#pragma unroll
            for (int g = 0; g < G; g++) {
                float4 y = make_float4(fmaxf(unpack_sum(a1[g][0]) + b1v.x, 0.f),
                                       fmaxf(unpack_sum(a1[g][1]) + b1v.y, 0.f),
                                       fmaxf(unpack_sum(a1[g][2]) + b1v.z, 0.f),
                                       fmaxf(unpack_sum(a1[g][3]) + b1v.w, 0.f));
                ((float4*)(myX + g * 256))[lane] = y;
            }
            __syncwarp();
            unsigned long long a2[G][4];
            gemm_p<G, 4, 32, 64>(sW2, myX, lane, a2);
#pragma unroll
            for (int g = 0; g < G; g++) {
                if (g < ne) {
                    float4 v = make_float4(unpack_sum(a2[g][0]) + b2v.x,
                                           unpack_sum(a2[g][1]) + b2v.y,
                                           unpack_sum(a2[g][2]) + b2v.z,
                                           unpack_sum(a2[g][3]) + b2v.w);
                    atomicAdd((float4*)&g_aggf[dc[g] * 128 + lane * 4], v);
                }
            }
            __syncwarp();
        }
    }
}

// ---------------- GRU (h == 0), fused s/f via blockIdx.y ----------------
#define GR_NW 8
#define GR_G 4
// smem floats: 49152 + 8*4*128 = 53248 -> 212992 B
__global__ void __launch_bounds__(256, 1)
k_gru(const float* __restrict__ Gs_bih, const float* __restrict__ Gs_bhh,
      const float* __restrict__ Gf_bih, const float* __restrict__ Gf_bhh,
      float* __restrict__ hs, float* __restrict__ hf, int level) {
    extern __shared__ float sm[];
    float* sW = sm;           // [384][128] staged wih (3 gate blocks of 128 rows)
    float* sX = sm + 49152;

    int t = blockIdx.y % 5;
    int isF = blockIdx.y / 5;
    int b = (level - 1) * 5 + t;
    int nS = g_noff[b], cnt = g_noff[b + 1] - nS;

    const float* agg = isF ? g_aggf : g_aggs;
    float* hout = isF ? hf : hs;
    const float* wgp = (isF ? g_Gfwih_t : g_Gswih_t) + t * 49152;
    const float* bih = (isF ? Gf_bih : Gs_bih) + t * 384;
    const float* bhh = (isF ? Gf_bhh : Gs_bhh) + t * 384;

    int w = threadIdx.x >> 5, lane = threadIdx.x & 31;
    int nw = gridDim.x * GR_NW;
    int wgi = blockIdx.x * GR_NW + w;
    int ws = nS + (int)(((long long)cnt * wgi) / nw);
    int we = nS + (int)(((long long)cnt * (wgi + 1)) / nw);
    float* myX = sX + w * GR_G * 128;

    float4 xr[GR_G];
    int nr[GR_G];
    {
        int nb = we - ws;
#pragma unroll
        for (int g = 0; g < GR_G; g++) {
            xr[g] = make_float4(0.f, 0.f, 0.f, 0.f);
            nr[g] = 0;
            if (g < nb) {
                nr[g] = g_nodes[ws + g];
                xr[g] = ((const float4*)(agg + nr[g] * 128))[lane];
            }
        }
    }
    stage_w_vec(sW, wgp, 3, 32, threadIdx.x, 256);
    // biases for outputs j = lane*4+oi of each gate block
    float4 bRi = ((const float4*)bih)[lane];
    float4 bRh = ((const float4*)bhh)[lane];
    float4 bZi = ((const float4*)(bih + 128))[lane];
    float4 bZh = ((const float4*)(bhh + 128))[lane];
    float4 bNi = ((const float4*)(bih + 256))[lane];
    float4 bNh = ((const float4*)(bhh + 256))[lane];
    float bR[4] = {bRi.x + bRh.x, bRi.y + bRh.y, bRi.z + bRh.z, bRi.w + bRh.w};
    float bZ[4] = {bZi.x + bZh.x, bZi.y + bZh.y, bZi.z + bZh.z, bZi.w + bZh.w};
    float bNiA[4] = {bNi.x, bNi.y, bNi.z, bNi.w};
    float bNhA[4] = {bNh.x, bNh.y, bNh.z, bNh.w};
    __syncthreads();

    for (int base = ws; base < we; base += GR_G) {
        int nn = min(GR_G, we - base);
        int nc[GR_G];
#pragma unroll
        for (int g = 0; g < GR_G; g++) {
            ((float4*)(myX + g * 128))[lane] = xr[g];
            nc[g] = nr[g];
        }
        __syncwarp();
        if (base + GR_G < we) {
            int nb = we - (base + GR_G);
#pragma unroll
            for (int g = 0; g < GR_G; g++) {
                xr[g] = make_float4(0.f, 0.f, 0.f, 0.f);
                nr[g] = 0;
                if (g < nb) {
                    nr[g] = g_nodes[base + GR_G + g];
                    xr[g] = ((const float4*)(agg + nr[g] * 128))[lane];
                }
            }
        }

        unsigned long long acc[GR_G][12];
        gemm_p<GR_G, 12, 32, 32>(sW, myX, lane, acc);

#pragma unroll
        for (int g = 0; g < GR_G; g++) {
            if (g < nn) {
                float o[4];
#pragma unroll
                for (int oi = 0; oi < 4; oi++) {
                    float r = sigmoidf_(unpack_sum(acc[g][oi]) + bR[oi]);
                    float z = sigmoidf_(unpack_sum(acc[g][oi + 4]) + bZ[oi]);
                    float n = tanhf(unpack_sum(acc[g][oi + 8]) + bNiA[oi] + r * bNhA[oi]);
                    o[oi] = (1.f - z) * n;
                }
                ((float4*)(hout + nc[g] * 128))[lane] = make_float4(o[0], o[1], o[2], o[3]);
            }
        }
        __syncwarp();
    }
}

// ---------------- host launch ----------------
extern "C" void kernel_launch(void* const* d_in, const int* in_sizes, int n_in,
                              void* d_out, int out_size) {
    const float* hs_init = (const float*)d_in[0];
    const float* Ws1 = (const float*)d_in[1];
    const float* bs1 = (const float*)d_in[2];
    const float* Ws2 = (const float*)d_in[3];
    const float* bs2 = (const float*)d_in[4];
    const float* Wf1 = (const float*)d_in[5];
    const float* bf1 = (const float*)d_in[6];
    const float* Wf2 = (const float*)d_in[7];
    const float* bf2 = (const float*)d_in[8];
    const float* Wnf1 = (const float*)d_in[9];
    const float* bnf1 = (const float*)d_in[10];
    const float* Wnf2 = (const float*)d_in[11];
    const float* bnf2 = (const float*)d_in[12];
    const float* Gs_wih = (const float*)d_in[13];
    // d_in[14] = Gs_whh (unused: h == 0)
    const float* Gs_bih = (const float*)d_in[15];
    const float* Gs_bhh = (const float*)d_in[16];
    const float* Gf_wih = (const float*)d_in[17];
    // d_in[18] = Gf_whh (unused)
    const float* Gf_bih = (const float*)d_in[19];
    const float* Gf_bhh = (const float*)d_in[20];
    const int* edge_index = (const int*)d_in[21];
    const int* gate = (const int*)d_in[22];
    const int* flev = (const int*)d_in[23];

    float* hs = (float*)d_out;
    float* hf = hs + NN * DD;

    cudaFuncSetAttribute(k_edges, cudaFuncAttributeMaxDynamicSharedMemorySize, 229376);
    cudaFuncSetAttribute(k_gru, cudaFuncAttributeMaxDynamicSharedMemorySize, 212992);

    k_init<<<1024, 256>>>(hs_init, gate, hs, hf, Ws1, Ws2, Wf1, Wf2, Wnf1, Wnf2,
                          Gs_wih, Gf_wih, edge_index, flev);
    k_scan<<<1, 1>>>();
    k_scatter<<<(EE + 255) / 256, 256>>>(edge_index, gate, flev);

    for (int level = 1; level < 5; level++) {
        k_edges<<<E_GRID, 256, 229376>>>(hs, hf, bs1, bs2, bf1, bf2, bnf1, bnf2, level);
        k_gru<<<dim3(14, 10), 256, 212992>>>(Gs_bih, Gs_bhh, Gf_bih, Gf_bhh, hs, hf, level);
    }
}